// round 1
// baseline (speedup 1.0000x reference)
#include <cuda_runtime.h>
#include <math.h>

#define SQ 1024
#define HD 4096
#define VOCAB 32000
#define KK2 8192          // 2*HD
#define TK 10
#define NDEPTH 5
#define NTOTAL 59
#define NFLAT (TK + NDEPTH*TK*TK)   // 510
#define NPAR (1 + NDEPTH*TK)        // 51

// ---------------- scratch (device globals; no allocation allowed) ----------------
__device__ float g_x[TK * KK2];          // concat(emb, hidden) rows
__device__ float g_fc[TK * HD];          // fc output
__device__ float g_hid[TK * HD];         // out_hidden (tanh)
__device__ float g_hid_sel[TK * HD];     // gathered input_hidden for next step
__device__ float g_logits[TK * VOCAB];
__device__ float g_topk_p[TK * TK];      // per-row top-k log-probs
__device__ int   g_topk_i[TK * TK];      // per-row top-k vocab ids
__device__ float g_scores[TK];           // cumulative path scores
__device__ int   g_cs_index[TK];         // last topk_cs_index
__device__ int   g_cur_ids[TK];
__device__ int   g_out_ids[TK];
__device__ float g_scores_flat[NFLAT];
__device__ int   g_tokens_flat[NFLAT];
__device__ int   g_parents_flat[NPAR];

// ---------------- build concat input rows ----------------
__global__ void build_x0_kernel(const float* __restrict__ hidden,
                                const int* __restrict__ input_ids,
                                const float* __restrict__ W_embed) {
    int j = blockIdx.x * blockDim.x + threadIdx.x;
    if (j < HD) {
        int id = input_ids[SQ];                      // ids[:, -1] == input_ids[0, S]
        g_x[j]      = W_embed[(size_t)id * HD + j];
        g_x[HD + j] = hidden[(size_t)(SQ - 1) * HD + j];
    }
}

__global__ void build_x_kernel(const float* __restrict__ W_embed) {
    int j = blockIdx.x * blockDim.x + threadIdx.x;
    int r = blockIdx.y;
    if (j < HD) {
        int id = g_cur_ids[r];
        g_x[(size_t)r * KK2 + j]      = W_embed[(size_t)id * HD + j];
        g_x[(size_t)r * KK2 + HD + j] = g_hid_sel[(size_t)r * HD + j];
    }
}

// ---------------- GEMV: out[r][n] = act(sum_k X[r][k] * W[n][k] + b[n]) ----------------
// warp computes 2 output columns for all R rows; float4 loads; X rows hot in L1/L2.
template <int R, bool TANH>
__global__ void __launch_bounds__(256)
gemv_kernel(const float* __restrict__ X, const float* __restrict__ W,
            const float* __restrict__ bias, float* __restrict__ out,
            int N, int K) {
    int warp = threadIdx.x >> 5;
    int lane = threadIdx.x & 31;
    int n0 = (blockIdx.x * 8 + warp) * 2;
    if (n0 >= N) return;
    const float4* W0 = (const float4*)(W + (size_t)n0 * K);
    const float4* W1 = (const float4*)(W + (size_t)(n0 + 1) * K);
    float acc0[R], acc1[R];
#pragma unroll
    for (int r = 0; r < R; ++r) { acc0[r] = 0.f; acc1[r] = 0.f; }
    const int nq = K >> 2;
    for (int q = lane; q < nq; q += 32) {
        float4 a = __ldg(W0 + q);
        float4 b = __ldg(W1 + q);
#pragma unroll
        for (int r = 0; r < R; ++r) {
            float4 xv = __ldg((const float4*)(X + (size_t)r * K) + q);
            acc0[r] += a.x * xv.x; acc0[r] += a.y * xv.y;
            acc0[r] += a.z * xv.z; acc0[r] += a.w * xv.w;
            acc1[r] += b.x * xv.x; acc1[r] += b.y * xv.y;
            acc1[r] += b.z * xv.z; acc1[r] += b.w * xv.w;
        }
    }
#pragma unroll
    for (int r = 0; r < R; ++r) {
#pragma unroll
        for (int off = 16; off > 0; off >>= 1) {
            acc0[r] += __shfl_down_sync(0xffffffffu, acc0[r], off);
            acc1[r] += __shfl_down_sync(0xffffffffu, acc1[r], off);
        }
    }
    if (lane == 0) {
        float b0 = bias ? bias[n0] : 0.f;
        float b1 = bias ? bias[n0 + 1] : 0.f;
#pragma unroll
        for (int r = 0; r < R; ++r) {
            float v0 = acc0[r] + b0;
            float v1 = acc1[r] + b1;
            if (TANH) { v0 = tanhf(v0); v1 = tanhf(v1); }
            out[(size_t)r * N + n0]     = v0;
            out[(size_t)r * N + n0 + 1] = v1;
        }
    }
}

// ---------------- per-row log-softmax + top-10 (tie-break: smaller index) ----------------
__global__ void softmax_topk_kernel() {
    int r = blockIdx.x;
    float* logits = g_logits + (size_t)r * VOCAB;
    __shared__ float s_val[256];
    __shared__ int   s_idx[256];
    int t = threadIdx.x;

    // row max
    float m = -INFINITY;
    for (int v = t; v < VOCAB; v += 256) m = fmaxf(m, logits[v]);
    s_val[t] = m;
    __syncthreads();
    for (int s = 128; s > 0; s >>= 1) {
        if (t < s) s_val[t] = fmaxf(s_val[t], s_val[t + s]);
        __syncthreads();
    }
    float rowmax = s_val[0];
    __syncthreads();

    // sum exp
    float sum = 0.f;
    for (int v = t; v < VOCAB; v += 256) sum += expf(logits[v] - rowmax);
    s_val[t] = sum;
    __syncthreads();
    for (int s = 128; s > 0; s >>= 1) {
        if (t < s) s_val[t] += s_val[t + s];
        __syncthreads();
    }
    float lse = rowmax + logf(s_val[0]);
    __syncthreads();

    // 10 rounds of block argmax (destructive), jax tie-break = lowest index
    for (int k = 0; k < TK; ++k) {
        float best = -INFINITY;
        int bi = 0x7fffffff;
        for (int v = t; v < VOCAB; v += 256) {
            float x = logits[v];
            if (x > best || (x == best && v < bi)) { best = x; bi = v; }
        }
        s_val[t] = best; s_idx[t] = bi;
        __syncthreads();
        for (int s = 128; s > 0; s >>= 1) {
            if (t < s) {
                float ov = s_val[t + s]; int oi = s_idx[t + s];
                if (ov > s_val[t] || (ov == s_val[t] && oi < s_idx[t])) {
                    s_val[t] = ov; s_idx[t] = oi;
                }
            }
            __syncthreads();
        }
        if (t == 0) {
            g_topk_p[r * TK + k] = s_val[0] - lse;
            g_topk_i[r * TK + k] = s_idx[0];
            logits[s_idx[0]] = -INFINITY;
        }
        __syncthreads();
    }
}

// ---------------- after the initial (pre-loop) top-k ----------------
__global__ void post0_kernel() {
    int j = blockIdx.x * blockDim.x + threadIdx.x;
    if (j < HD) {
        float v = g_hid[j];   // last_hidden broadcast to all 10 rows
#pragma unroll
        for (int r = 0; r < TK; ++r) g_hid_sel[(size_t)r * HD + j] = v;
    }
    if (blockIdx.x == 0 && j < TK) {
        float p = g_topk_p[j];
        int id = g_topk_i[j];
        g_scores[j] = p;
        g_scores_flat[j] = p;
        g_tokens_flat[j] = id;
        g_cur_ids[j] = id;
        g_cs_index[j] = j;
        if (j == 0) g_parents_flat[0] = 0;
    }
}

// ---------------- cross-row merge for depth iteration `iter` ----------------
__global__ void combine_kernel(int iter) {
    __shared__ float cu[TK * TK];
    __shared__ float sc_old[TK];
    __shared__ int prev_cs[TK];
    int t = threadIdx.x;
    if (t < TK) { sc_old[t] = g_scores[t]; prev_cs[t] = g_cs_index[t]; }
    __syncthreads();
    if (t < TK * TK) cu[t] = g_topk_p[t] + sc_old[t / TK];
    __syncthreads();
    if (t < TK * TK) {
        g_scores_flat[TK + iter * 100 + t] = cu[t];
        g_tokens_flat[TK + iter * 100 + t] = g_topk_i[t];
    }
    if (t < TK) {
        int bias1 = (iter > 0) ? TK : 0;
        int bias2 = (iter > 1) ? (iter - 1) : 0;
        int bias = 1 + TK * TK * bias2 + bias1;
        g_parents_flat[1 + iter * TK + t] = prev_cs[t] + bias;
    }
    __syncthreads();
    if (t == 0) {
        bool used[TK * TK];
        for (int j = 0; j < TK * TK; ++j) used[j] = false;
        for (int k = 0; k < TK; ++k) {
            float best = -INFINITY; int bi = 0;
            for (int j = 0; j < TK * TK; ++j)
                if (!used[j] && cu[j] > best) { best = cu[j]; bi = j; }
            used[bi] = true;
            g_scores[k]   = best;
            g_cs_index[k] = bi;
            g_out_ids[k]  = bi / TK;
            g_cur_ids[k]  = g_topk_i[bi];
        }
    }
}

__global__ void gather_hidden_kernel() {
    int j = blockIdx.x * blockDim.x + threadIdx.x;
    int r = blockIdx.y;
    if (j < HD)
        g_hid_sel[(size_t)r * HD + j] = g_hid[(size_t)g_out_ids[r] * HD + j];
}

// ---------------- final: top-59, sort, parents, tree mask, outputs ----------------
__global__ void finalize_kernel(const int* __restrict__ input_ids, float* __restrict__ out) {
    __shared__ float sc[NFLAT];
    __shared__ int top_idx[NTOTAL];
    __shared__ int mask_idx[NTOTAL];
    __shared__ unsigned long long rows[NTOTAL + 1];
    int t = threadIdx.x, T = blockDim.x;
    for (int j = t; j < NFLAT; j += T) sc[j] = g_scores_flat[j];
    __syncthreads();
    if (t == 0) {
        // top-59 (strict > keeps lowest index on ties, matching jax)
        for (int k = 0; k < NTOTAL; ++k) {
            float best = -INFINITY; int bi = 0;
            for (int j = 0; j < NFLAT; ++j)
                if (sc[j] > best) { best = sc[j]; bi = j; }
            top_idx[k] = bi;
            sc[bi] = -INFINITY;
        }
        // sort indices ascending
        for (int a = 1; a < NTOTAL; ++a) {
            int v = top_idx[a], b = a - 1;
            while (b >= 0 && top_idx[b] > v) { top_idx[b + 1] = top_idx[b]; --b; }
            top_idx[b + 1] = v;
        }
    }
    __syncthreads();
    if (t == 0) out[0] = (float)input_ids[SQ];   // sample_token
    for (int k = t; k < NTOTAL; k += T) {
        int idx = top_idx[k];
        out[1 + k]  = (float)g_tokens_flat[idx]; // draft_tokens[1..59]
        out[60 + k] = g_scores_flat[idx];        // top_vals
    }
    __syncthreads();
    if (t == 0) {
        for (int k = 0; k < NTOTAL; ++k) {
            int p = g_parents_flat[top_idx[k] / TK];
            int mi;
            if (p == 0) {
                mi = 0;  // (-1) + 1
            } else {
                int target = p - 1;
                int lo = 0, hi = NTOTAL;       // searchsorted left
                while (lo < hi) {
                    int mid = (lo + hi) >> 1;
                    if (top_idx[mid] < target) lo = mid + 1; else hi = mid;
                }
                mi = lo + 1;
            }
            mask_idx[k] = mi;
        }
        for (int r = 0; r < NTOTAL + 1; ++r)
            rows[r] = (1ULL << r) | 1ULL;       // eye + col0
        for (int i = 0; i < NTOTAL; ++i) {
            int src = mask_idx[i];
            if (src > NTOTAL) src = NTOTAL;      // jnp OOB clamp
            rows[i + 1] |= rows[src];
        }
    }
    __syncthreads();
    for (int e = t; e < (NTOTAL + 1) * (NTOTAL + 1); e += T) {
        int r = e / (NTOTAL + 1), c = e % (NTOTAL + 1);
        out[119 + e] = ((rows[r] >> c) & 1ULL) ? 1.0f : 0.0f;   // tree_mask
    }
    for (int r = t; r < NTOTAL + 1; r += T)
        out[3719 + r] = (float)(__popcll(rows[r]) - 1);         // tree_position_ids
}

// ---------------- launch ----------------
extern "C" void kernel_launch(void* const* d_in, const int* in_sizes, int n_in,
                              void* d_out, int out_size) {
    const float* hidden    = (const float*)d_in[0];
    const int*   input_ids = (const int*)d_in[1];
    const float* W_embed   = (const float*)d_in[2];
    const float* W_head    = (const float*)d_in[3];
    const float* W_fc      = (const float*)d_in[4];
    const float* b_fc      = (const float*)d_in[5];
    const float* W_m       = (const float*)d_in[6];
    const float* b_m       = (const float*)d_in[7];
    float* out = (float*)d_out;

    float *p_x, *p_fc, *p_hid, *p_logits;
    cudaGetSymbolAddress((void**)&p_x,      g_x);
    cudaGetSymbolAddress((void**)&p_fc,     g_fc);
    cudaGetSymbolAddress((void**)&p_hid,    g_hid);
    cudaGetSymbolAddress((void**)&p_logits, g_logits);

    // ---- initial step (only last position matters) ----
    build_x0_kernel<<<HD / 256, 256>>>(hidden, input_ids, W_embed);
    gemv_kernel<1, false><<<HD / 16, 256>>>(p_x, W_fc, b_fc, p_fc, HD, KK2);
    gemv_kernel<1, true ><<<HD / 16, 256>>>(p_fc, W_m, b_m, p_hid, HD, HD);
    gemv_kernel<1, false><<<VOCAB / 16, 256>>>(p_hid, W_head, nullptr, p_logits, VOCAB, HD);
    softmax_topk_kernel<<<1, 256>>>();
    post0_kernel<<<HD / 256, 256>>>();

    // ---- depth loop ----
    for (int i = 0; i < NDEPTH; ++i) {
        build_x_kernel<<<dim3(HD / 256, TK), 256>>>(W_embed);
        gemv_kernel<TK, false><<<HD / 16, 256>>>(p_x, W_fc, b_fc, p_fc, HD, KK2);
        gemv_kernel<TK, true ><<<HD / 16, 256>>>(p_fc, W_m, b_m, p_hid, HD, HD);
        gemv_kernel<TK, false><<<VOCAB / 16, 256>>>(p_hid, W_head, nullptr, p_logits, VOCAB, HD);
        softmax_topk_kernel<<<TK, 256>>>();
        combine_kernel<<<1, 128>>>(i);
        if (i < NDEPTH - 1)
            gather_hidden_kernel<<<dim3(HD / 256, TK), 256>>>();
    }

    finalize_kernel<<<1, 256>>>(input_ids, out);
    (void)in_sizes; (void)n_in; (void)out_size;
}